// round 10
// baseline (speedup 1.0000x reference)
#include <cuda_runtime.h>
#include <stdint.h>
#include <math.h>

#define Bn 8
#define Mn 1024
#define Nn 100
#define ROI 128
#define FGP 64

__device__ float g_mo[Bn * Mn];
__device__ int   g_asgn[Bn * Mn];

// ---------------------------------------------------------------------------
// threefry-2x32 (JAX PRNG core)
// ---------------------------------------------------------------------------
__device__ __forceinline__ uint32_t rotl32(uint32_t x, int d) {
    return (x << d) | (x >> (32 - d));
}

__device__ __forceinline__ void tf2x32(uint32_t k0, uint32_t k1,
                                       uint32_t x0, uint32_t x1,
                                       uint32_t &o0, uint32_t &o1) {
    uint32_t ks2 = k0 ^ k1 ^ 0x1BD11BDAu;
    x0 += k0; x1 += k1;
#define TF_R(r) { x0 += x1; x1 = rotl32(x1, r); x1 ^= x0; }
    TF_R(13) TF_R(15) TF_R(26) TF_R(6)   x0 += k1;  x1 += ks2 + 1u;
    TF_R(17) TF_R(29) TF_R(16) TF_R(24)  x0 += ks2; x1 += k0 + 2u;
    TF_R(13) TF_R(15) TF_R(26) TF_R(6)   x0 += k0;  x1 += k1 + 3u;
    TF_R(17) TF_R(29) TF_R(16) TF_R(24)  x0 += k1;  x1 += ks2 + 4u;
    TF_R(13) TF_R(15) TF_R(26) TF_R(6)   x0 += ks2; x1 += k0 + 5u;
#undef TF_R
    o0 = x0; o1 = x1;
}

// partitionable-mode 32-bit random bits for element i under key (k0,k1)
__device__ __forceinline__ uint32_t tf_bits32(uint32_t k0, uint32_t k1, uint32_t i) {
    uint32_t o0, o1;
    tf2x32(k0, k1, 0u, i, o0, o1);
    return o0 ^ o1;
}

__device__ __forceinline__ float u01(uint32_t bits) {
    return __uint_as_float((bits >> 9) | 0x3F800000u) - 1.0f;
}

// ---------------------------------------------------------------------------
// rotated 3D IoU of one pair (mirrors reference _pair_iou3d, float32)
// ---------------------------------------------------------------------------
__device__ float pair_iou3d(const float a[7], const float b[7]) {
    // height overlap (exact-zero fast path matches reference)
    float oh = fminf(a[2] + a[5] * 0.5f, b[2] + b[5] * 0.5f)
             - fmaxf(a[2] - a[5] * 0.5f, b[2] - b[5] * 0.5f);
    oh = fmaxf(oh, 0.0f);
    if (oh <= 0.0f) return 0.0f;

    // BEV circumcircle reject (disjoint => reference polygon area is exactly 0)
    {
        float ddx = a[0] - b[0], ddy = a[1] - b[1];
        float ra = 0.5f * sqrtf(a[3] * a[3] + a[4] * a[4]);
        float rb = 0.5f * sqrtf(b[3] * b[3] + b[4] * b[4]);
        float rr = ra + rb + 1e-4f;   // margin covers the 1e-6 inside-test slack
        if (ddx * ddx + ddy * ddy > rr * rr) return 0.0f;
    }

    float csa = cosf(a[6]), sna = sinf(a[6]);
    float csb = cosf(b[6]), snb = sinf(b[6]);

    float cax[4], cay[4], cbx[4], cby[4];
    {
        const float sx[4] = {1.f, 1.f, -1.f, -1.f};
        const float sy[4] = {1.f, -1.f, -1.f, 1.f};
        float hxa = a[3] * 0.5f, hya = a[4] * 0.5f;
        float hxb = b[3] * 0.5f, hyb = b[4] * 0.5f;
#pragma unroll
        for (int k = 0; k < 4; k++) {
            float lx = sx[k] * hxa, ly = sy[k] * hya;
            cax[k] = lx * csa - ly * sna + a[0];
            cay[k] = lx * sna + ly * csa + a[1];
            lx = sx[k] * hxb; ly = sy[k] * hyb;
            cbx[k] = lx * csb - ly * snb + b[0];
            cby[k] = lx * snb + ly * csb + b[1];
        }
    }

    float px[24], py[24];
    int nv = 0;

    // 16 edge-edge intersections (same i-major, j-minor order as reference)
#pragma unroll
    for (int i = 0; i < 4; i++) {
        float a1x = cax[i], a1y = cay[i];
        float d1x = cax[(i + 1) & 3] - a1x;
        float d1y = cay[(i + 1) & 3] - a1y;
#pragma unroll
        for (int j = 0; j < 4; j++) {
            float b1x = cbx[j], b1y = cby[j];
            float d2x = cbx[(j + 1) & 3] - b1x;
            float d2y = cby[(j + 1) & 3] - b1y;
            float den = d1x * d2y - d1y * d2x;
            if (fabsf(den) > 1e-8f) {
                float dfx = b1x - a1x, dfy = b1y - a1y;
                float tt = (dfx * d2y - dfy * d2x) / den;
                float uu = (dfx * d1y - dfy * d1x) / den;
                if (tt >= 0.0f && tt <= 1.0f && uu >= 0.0f && uu <= 1.0f) {
                    px[nv] = a1x + tt * d1x;
                    py[nv] = a1y + tt * d1y;
                    nv++;
                }
            }
        }
    }
    // a corners inside b, then b corners inside a (reference order)
#pragma unroll
    for (int k = 0; k < 4; k++) {
        float rx = cax[k] - b[0], ry = cay[k] - b[1];
        float lx = rx * csb + ry * snb;
        float ly = -rx * snb + ry * csb;
        if (fabsf(lx) <= b[3] * 0.5f + 1e-6f && fabsf(ly) <= b[4] * 0.5f + 1e-6f) {
            px[nv] = cax[k]; py[nv] = cay[k]; nv++;
        }
    }
#pragma unroll
    for (int k = 0; k < 4; k++) {
        float rx = cbx[k] - a[0], ry = cby[k] - a[1];
        float lx = rx * csa + ry * sna;
        float ly = -rx * sna + ry * csa;
        if (fabsf(lx) <= a[3] * 0.5f + 1e-6f && fabsf(ly) <= a[4] * 0.5f + 1e-6f) {
            px[nv] = cbx[k]; py[nv] = cby[k]; nv++;
        }
    }

    float area = 0.0f;
    if (nv > 0) {
        float sx = 0.0f, sy = 0.0f;
        for (int k = 0; k < nv; k++) { sx += px[k]; sy += py[k]; }
        float ctx = sx / (float)nv, cty = sy / (float)nv;

        float ang[24];
        for (int k = 0; k < nv; k++) {
            px[k] -= ctx; py[k] -= cty;
            ang[k] = atan2f(py[k], px[k]);
        }
        // stable insertion sort by angle (matches stable argsort on push order)
        for (int i = 1; i < nv; i++) {
            float ka = ang[i], kx = px[i], ky = py[i];
            int j = i - 1;
            while (j >= 0 && ang[j] > ka) {
                ang[j + 1] = ang[j]; px[j + 1] = px[j]; py[j + 1] = py[j];
                j--;
            }
            ang[j + 1] = ka; px[j + 1] = kx; py[j + 1] = ky;
        }
        float s2 = 0.0f;
        for (int k = 0; k < nv; k++) {
            int n2 = (k + 1 == nv) ? 0 : k + 1;
            s2 += px[k] * py[n2] - py[k] * px[n2];
        }
        area = 0.5f * fabsf(s2);
    }

    float inter = area * oh;
    float va = a[3] * a[4] * a[5];
    float vb = b[3] * b[4] * b[5];
    return inter / fmaxf(va + vb - inter, 1e-6f);
}

// ---------------------------------------------------------------------------
// Kernel 1: per-(b,roi) block, thread-per-gt IoU, first-max argmax reduction
// ---------------------------------------------------------------------------
__global__ __launch_bounds__(128) void iou_kernel(const float* __restrict__ rois,
                                                  const float* __restrict__ gts) {
    int bm = blockIdx.x;             // b*Mn + m
    int b = bm >> 10;
    int t = threadIdx.x;

    __shared__ float a7[7];
    __shared__ int s_last;
    __shared__ float sval[128];
    __shared__ int sidx[128];

    if (t < 7) a7[t] = rois[(size_t)bm * 7 + t];
    if (t == 0) s_last = -1;
    __syncthreads();

    float gbox[8];
    if (t < Nn) {
        const float* g = gts + ((size_t)b * Nn + t) * 8;
        float s = 0.0f;
#pragma unroll
        for (int k = 0; k < 8; k++) { gbox[k] = g[k]; s += gbox[k]; }
        if (s != 0.0f) atomicMax(&s_last, t);
    }
    __syncthreads();

    float val = -2.0f;
    if (t < Nn) {
        if (t <= s_last) val = pair_iou3d(a7, gbox);
        else             val = -1.0f;
    }
    sval[t] = val;
    sidx[t] = t;
    __syncthreads();

    for (int s = 64; s > 0; s >>= 1) {
        if (t < s) {
            float v2 = sval[t + s]; int i2 = sidx[t + s];
            if (v2 > sval[t] || (v2 == sval[t] && i2 < sidx[t])) {
                sval[t] = v2; sidx[t] = i2;
            }
        }
        __syncthreads();
    }
    if (t == 0) {
        g_mo[bm] = sval[0];
        g_asgn[bm] = sidx[0];
    }
}

// ---------------------------------------------------------------------------
// Kernel 2: per-batch sampling + output writes
// ---------------------------------------------------------------------------
__device__ __forceinline__ int rpick(float u, const int* asc, int n) {
    int v = (int)(u * (float)n);           // truncation like .astype(int32)
    int hi = (n - 1 > 0) ? (n - 1) : 0;
    if (v < 0) v = 0;
    if (v > hi) v = hi;
    return asc[v];
}

__global__ __launch_bounds__(256) void sample_kernel(
    const float* __restrict__ rois, const float* __restrict__ gts,
    const float* __restrict__ scores, const int* __restrict__ labels,
    float* __restrict__ out) {
    int b = blockIdx.x;
    int t = threadIdx.x;
    int lane = t & 31, warp = t >> 5;

    __shared__ float s_u1[Mn];
    __shared__ float s_u2[ROI], s_u3[ROI], s_u4[ROI];
    __shared__ float s_mo[Mn];
    __shared__ unsigned char s_cat[Mn];
    __shared__ float s_key[Mn];
    __shared__ int s_sidx[Mn];
    __shared__ int s_fgasc[Mn], s_hdasc[Mn], s_ezasc[Mn];
    __shared__ int s_ccnt[32];
    __shared__ int s_coff[33];
    __shared__ int s_n[3];
    __shared__ uint32_t s_kk[4][2];

    // keys: master = key(42) = (0,42); split(8)[b]; split(4) -> k1..k4
    if (t == 0) {
        uint32_t kb0, kb1;
        tf2x32(0u, 42u, 0u, (uint32_t)b, kb0, kb1);
        for (int q = 0; q < 4; q++) {
            uint32_t o0, o1;
            tf2x32(kb0, kb1, 0u, (uint32_t)q, o0, o1);
            s_kk[q][0] = o0; s_kk[q][1] = o1;
        }
        s_fgasc[0] = 0; s_hdasc[0] = 0; s_ezasc[0] = 0;
    }
    __syncthreads();

    for (int i = t; i < Mn; i += 256)
        s_u1[i] = u01(tf_bits32(s_kk[0][0], s_kk[0][1], (uint32_t)i));
    if (t < ROI) {
        s_u2[t] = u01(tf_bits32(s_kk[1][0], s_kk[1][1], (uint32_t)t));
        s_u3[t] = u01(tf_bits32(s_kk[2][0], s_kk[2][1], (uint32_t)t));
        s_u4[t] = u01(tf_bits32(s_kk[3][0], s_kk[3][1], (uint32_t)t));
    }

    for (int i = t; i < Mn; i += 256) {
        float mo = g_mo[b * Mn + i];
        s_mo[i] = mo;
        s_cat[i] = (mo >= 0.55f) ? 0 : ((mo < 0.1f) ? 2 : 1);
    }
    __syncthreads();

    // ballot-based ascending index lists per category
    for (int c = 0; c < 3; c++) {
        int* asc = (c == 0) ? s_fgasc : ((c == 1) ? s_hdasc : s_ezasc);
        for (int seg = 0; seg < 4; seg++) {
            int e = seg * 256 + t;
            bool mf = (s_cat[e] == c);
            unsigned bal = __ballot_sync(0xffffffffu, mf);
            if (lane == 0) s_ccnt[seg * 8 + warp] = __popc(bal);
        }
        __syncthreads();
        if (t == 0) {
            int acc = 0;
            for (int k = 0; k < 32; k++) { s_coff[k] = acc; acc += s_ccnt[k]; }
            s_coff[32] = acc;
            s_n[c] = acc;
        }
        __syncthreads();
        for (int seg = 0; seg < 4; seg++) {
            int e = seg * 256 + t;
            bool mf = (s_cat[e] == c);
            unsigned bal = __ballot_sync(0xffffffffu, mf);
            int rank = __popc(bal & ((1u << lane) - 1u));
            if (mf) asc[s_coff[seg * 8 + warp] + rank] = e;
        }
        __syncthreads();
    }

    // bitonic sort of (key, idx): key = fg ? u1 : 2.0, stable via idx tie-break
    for (int i = t; i < Mn; i += 256) {
        s_key[i] = (s_cat[i] == 0) ? s_u1[i] : 2.0f;
        s_sidx[i] = i;
    }
    __syncthreads();
    for (int k = 2; k <= Mn; k <<= 1) {
        for (int j2 = k >> 1; j2 > 0; j2 >>= 1) {
            for (int i = t; i < Mn; i += 256) {
                int ix = i ^ j2;
                if (ix > i) {
                    bool up = ((i & k) == 0);
                    float v1 = s_key[i], v2 = s_key[ix];
                    int i1 = s_sidx[i], i2 = s_sidx[ix];
                    bool gtr = (v1 > v2) || (v1 == v2 && i1 > i2);
                    if (gtr == up) {
                        s_key[i] = v2; s_key[ix] = v1;
                        s_sidx[i] = i2; s_sidx[ix] = i1;
                    }
                }
            }
            __syncthreads();
        }
    }

    int n_fg = s_n[0], n_hard = s_n[1], n_easy = s_n[2];
    int n_bg = n_hard + n_easy;
    int fg_this = (n_fg > 0) ? ((n_bg > 0) ? ((FGP < n_fg) ? FGP : n_fg) : ROI) : 0;
    int bg_this = ROI - fg_this;
    int hard_num = (n_hard > 0 && n_easy > 0) ? (int)((float)bg_this * 0.8f)
                 : ((n_hard > 0) ? bg_this : 0);

    if (t < ROI) {
        int j = t;
        int rand_fg = rpick(s_u2[j], s_fgasc, n_fg);
        int hp      = rpick(s_u3[j], s_hdasc, n_hard);
        int ep      = rpick(s_u4[j], s_ezasc, n_easy);
        int fg_idx = (n_bg > 0) ? s_sidx[j] : rand_fg;
        int bg_idx = ((j - fg_this) < hard_num) ? hp : ep;
        int idx = (j < fg_this) ? fg_idx : bg_idx;

        int gidx = b * Mn + idx;
        int base = b * ROI + j;
        float iou = s_mo[idx];

        const float* r = rois + (size_t)gidx * 7;
        float* o_r = out + (size_t)base * 7;
#pragma unroll
        for (int k = 0; k < 7; k++) o_r[k] = r[k];

        int asg = g_asgn[gidx];
        const float* g = gts + ((size_t)(b * Nn + asg)) * 8;
        float* o_g = out + 7168 + (size_t)base * 8;
#pragma unroll
        for (int k = 0; k < 8; k++) o_g[k] = g[k];

        out[15360 + base] = iou;
        out[16384 + base] = scores[gidx];
        out[17408 + base] = (float)labels[gidx];
        bool fgc = iou > 0.75f;
        bool bgc = iou < 0.25f;
        out[18432 + base] = (!fgc && !bgc) ? (iou * 2.0f - 0.5f) : (fgc ? 1.0f : 0.0f);
        out[19456 + base] = (iou > 0.55f) ? 1.0f : 0.0f;
    }
}

// ---------------------------------------------------------------------------
extern "C" void kernel_launch(void* const* d_in, const int* in_sizes, int n_in,
                              void* d_out, int out_size) {
    const float* rois   = (const float*)d_in[0];
    const float* gts    = (const float*)d_in[1];
    const float* scores = (const float*)d_in[2];
    const int*   labels = (const int*)d_in[3];
    float* out = (float*)d_out;

    iou_kernel<<<Bn * Mn, 128>>>(rois, gts);
    sample_kernel<<<Bn, 256>>>(rois, gts, scores, labels, out);
}

// round 11
// speedup vs baseline: 1.0288x; 1.0288x over previous
#include <cuda_runtime.h>
#include <stdint.h>
#include <math.h>

#define Bn 8
#define Mn 1024
#define Nn 100
#define ROI 128
#define FGP 64

__device__ float g_mo[Bn * Mn];
__device__ int   g_asgn[Bn * Mn];

// ---------------------------------------------------------------------------
// threefry-2x32 (JAX PRNG core)
// ---------------------------------------------------------------------------
__device__ __forceinline__ uint32_t rotl32(uint32_t x, int d) {
    return (x << d) | (x >> (32 - d));
}

__device__ __forceinline__ void tf2x32(uint32_t k0, uint32_t k1,
                                       uint32_t x0, uint32_t x1,
                                       uint32_t &o0, uint32_t &o1) {
    uint32_t ks2 = k0 ^ k1 ^ 0x1BD11BDAu;
    x0 += k0; x1 += k1;
#define TF_R(r) { x0 += x1; x1 = rotl32(x1, r); x1 ^= x0; }
    TF_R(13) TF_R(15) TF_R(26) TF_R(6)   x0 += k1;  x1 += ks2 + 1u;
    TF_R(17) TF_R(29) TF_R(16) TF_R(24)  x0 += ks2; x1 += k0 + 2u;
    TF_R(13) TF_R(15) TF_R(26) TF_R(6)   x0 += k0;  x1 += k1 + 3u;
    TF_R(17) TF_R(29) TF_R(16) TF_R(24)  x0 += k1;  x1 += ks2 + 4u;
    TF_R(13) TF_R(15) TF_R(26) TF_R(6)   x0 += ks2; x1 += k0 + 5u;
#undef TF_R
    o0 = x0; o1 = x1;
}

// partitionable-mode 32-bit random bits for element i under key (k0,k1)
__device__ __forceinline__ uint32_t tf_bits32(uint32_t k0, uint32_t k1, uint32_t i) {
    uint32_t o0, o1;
    tf2x32(k0, k1, 0u, i, o0, o1);
    return o0 ^ o1;
}

__device__ __forceinline__ float u01(uint32_t bits) {
    return __uint_as_float((bits >> 9) | 0x3F800000u) - 1.0f;
}

// ---------------------------------------------------------------------------
// rotated 3D IoU of one pair (mirrors reference _pair_iou3d, float32)
// ---------------------------------------------------------------------------
__device__ float pair_iou3d(const float a[7], const float b[7]) {
    // height overlap (exact-zero fast path matches reference)
    float oh = fminf(a[2] + a[5] * 0.5f, b[2] + b[5] * 0.5f)
             - fmaxf(a[2] - a[5] * 0.5f, b[2] - b[5] * 0.5f);
    oh = fmaxf(oh, 0.0f);
    if (oh <= 0.0f) return 0.0f;

    // BEV circumcircle reject (disjoint => reference polygon area is exactly 0)
    {
        float ddx = a[0] - b[0], ddy = a[1] - b[1];
        float ra = 0.5f * sqrtf(a[3] * a[3] + a[4] * a[4]);
        float rb = 0.5f * sqrtf(b[3] * b[3] + b[4] * b[4]);
        float rr = ra + rb + 1e-4f;   // margin covers the 1e-6 inside-test slack
        if (ddx * ddx + ddy * ddy > rr * rr) return 0.0f;
    }

    float csa = cosf(a[6]), sna = sinf(a[6]);
    float csb = cosf(b[6]), snb = sinf(b[6]);

    float cax[4], cay[4], cbx[4], cby[4];
    {
        const float sx[4] = {1.f, 1.f, -1.f, -1.f};
        const float sy[4] = {1.f, -1.f, -1.f, 1.f};
        float hxa = a[3] * 0.5f, hya = a[4] * 0.5f;
        float hxb = b[3] * 0.5f, hyb = b[4] * 0.5f;
#pragma unroll
        for (int k = 0; k < 4; k++) {
            float lx = sx[k] * hxa, ly = sy[k] * hya;
            cax[k] = lx * csa - ly * sna + a[0];
            cay[k] = lx * sna + ly * csa + a[1];
            lx = sx[k] * hxb; ly = sy[k] * hyb;
            cbx[k] = lx * csb - ly * snb + b[0];
            cby[k] = lx * snb + ly * csb + b[1];
        }
    }

    float px[24], py[24];
    int nv = 0;

    // 16 edge-edge intersections (same i-major, j-minor order as reference)
#pragma unroll
    for (int i = 0; i < 4; i++) {
        float a1x = cax[i], a1y = cay[i];
        float d1x = cax[(i + 1) & 3] - a1x;
        float d1y = cay[(i + 1) & 3] - a1y;
#pragma unroll
        for (int j = 0; j < 4; j++) {
            float b1x = cbx[j], b1y = cby[j];
            float d2x = cbx[(j + 1) & 3] - b1x;
            float d2y = cby[(j + 1) & 3] - b1y;
            float den = d1x * d2y - d1y * d2x;
            if (fabsf(den) > 1e-8f) {
                float dfx = b1x - a1x, dfy = b1y - a1y;
                float tt = (dfx * d2y - dfy * d2x) / den;
                float uu = (dfx * d1y - dfy * d1x) / den;
                if (tt >= 0.0f && tt <= 1.0f && uu >= 0.0f && uu <= 1.0f) {
                    px[nv] = a1x + tt * d1x;
                    py[nv] = a1y + tt * d1y;
                    nv++;
                }
            }
        }
    }
    // a corners inside b, then b corners inside a (reference order)
#pragma unroll
    for (int k = 0; k < 4; k++) {
        float rx = cax[k] - b[0], ry = cay[k] - b[1];
        float lx = rx * csb + ry * snb;
        float ly = -rx * snb + ry * csb;
        if (fabsf(lx) <= b[3] * 0.5f + 1e-6f && fabsf(ly) <= b[4] * 0.5f + 1e-6f) {
            px[nv] = cax[k]; py[nv] = cay[k]; nv++;
        }
    }
#pragma unroll
    for (int k = 0; k < 4; k++) {
        float rx = cbx[k] - a[0], ry = cby[k] - a[1];
        float lx = rx * csa + ry * sna;
        float ly = -rx * sna + ry * csa;
        if (fabsf(lx) <= a[3] * 0.5f + 1e-6f && fabsf(ly) <= a[4] * 0.5f + 1e-6f) {
            px[nv] = cbx[k]; py[nv] = cby[k]; nv++;
        }
    }

    float area = 0.0f;
    if (nv > 0) {
        float sx = 0.0f, sy = 0.0f;
        for (int k = 0; k < nv; k++) { sx += px[k]; sy += py[k]; }
        float ctx = sx / (float)nv, cty = sy / (float)nv;

        float ang[24];
        for (int k = 0; k < nv; k++) {
            px[k] -= ctx; py[k] -= cty;
            ang[k] = atan2f(py[k], px[k]);
        }
        // stable insertion sort by angle (matches stable argsort on push order)
        for (int i = 1; i < nv; i++) {
            float ka = ang[i], kx = px[i], ky = py[i];
            int j = i - 1;
            while (j >= 0 && ang[j] > ka) {
                ang[j + 1] = ang[j]; px[j + 1] = px[j]; py[j + 1] = py[j];
                j--;
            }
            ang[j + 1] = ka; px[j + 1] = kx; py[j + 1] = ky;
        }
        float s2 = 0.0f;
        for (int k = 0; k < nv; k++) {
            int n2 = (k + 1 == nv) ? 0 : k + 1;
            s2 += px[k] * py[n2] - py[k] * px[n2];
        }
        area = 0.5f * fabsf(s2);
    }

    float inter = area * oh;
    float va = a[3] * a[4] * a[5];
    float vb = b[3] * b[4] * b[5];
    return inter / fmaxf(va + vb - inter, 1e-6f);
}

// ---------------------------------------------------------------------------
// Kernel 1: per-(b,roi) block, thread-per-gt IoU, first-max argmax reduction
// ---------------------------------------------------------------------------
__global__ __launch_bounds__(128) void iou_kernel(const float* __restrict__ rois,
                                                  const float* __restrict__ gts) {
    int bm = blockIdx.x;             // b*Mn + m
    int b = bm >> 10;
    int t = threadIdx.x;

    __shared__ float a7[7];
    __shared__ int s_last;
    __shared__ float sval[128];
    __shared__ int sidx[128];

    if (t < 7) a7[t] = rois[(size_t)bm * 7 + t];
    if (t == 0) s_last = -1;
    __syncthreads();

    float gbox[8];
    if (t < Nn) {
        const float* g = gts + ((size_t)b * Nn + t) * 8;
        float s = 0.0f;
#pragma unroll
        for (int k = 0; k < 8; k++) { gbox[k] = g[k]; s += gbox[k]; }
        if (s != 0.0f) atomicMax(&s_last, t);
    }
    __syncthreads();

    float val = -2.0f;
    if (t < Nn) {
        if (t <= s_last) val = pair_iou3d(a7, gbox);
        else             val = -1.0f;
    }
    sval[t] = val;
    sidx[t] = t;
    __syncthreads();

    for (int s = 64; s > 0; s >>= 1) {
        if (t < s) {
            float v2 = sval[t + s]; int i2 = sidx[t + s];
            if (v2 > sval[t] || (v2 == sval[t] && i2 < sidx[t])) {
                sval[t] = v2; sidx[t] = i2;
            }
        }
        __syncthreads();
    }
    if (t == 0) {
        g_mo[bm] = sval[0];
        g_asgn[bm] = sidx[0];
    }
}

// ---------------------------------------------------------------------------
// Kernel 2: per-batch sampling + output writes
// ---------------------------------------------------------------------------
__device__ __forceinline__ int rpick(float u, const int* asc, int n) {
    int v = (int)(u * (float)n);           // truncation like .astype(int32)
    int hi = (n - 1 > 0) ? (n - 1) : 0;
    if (v < 0) v = 0;
    if (v > hi) v = hi;
    return asc[v];
}

__global__ __launch_bounds__(256) void sample_kernel(
    const float* __restrict__ rois, const float* __restrict__ gts,
    const float* __restrict__ scores, const int* __restrict__ labels,
    float* __restrict__ out) {
    int b = blockIdx.x;
    int t = threadIdx.x;
    int lane = t & 31, warp = t >> 5;

    __shared__ float s_u1[Mn];
    __shared__ float s_u2[ROI], s_u3[ROI], s_u4[ROI];
    __shared__ float s_mo[Mn];
    __shared__ unsigned char s_cat[Mn];
    __shared__ float s_key[Mn];
    __shared__ int s_sidx[Mn];
    __shared__ int s_fgasc[Mn], s_hdasc[Mn], s_ezasc[Mn];
    __shared__ int s_ccnt[32];
    __shared__ int s_coff[33];
    __shared__ int s_n[3];
    __shared__ uint32_t s_kk[4][2];

    // keys: master = key(42) = (0,42); split(8)[b]; split(4) -> k1..k4
    if (t == 0) {
        uint32_t kb0, kb1;
        tf2x32(0u, 42u, 0u, (uint32_t)b, kb0, kb1);
        for (int q = 0; q < 4; q++) {
            uint32_t o0, o1;
            tf2x32(kb0, kb1, 0u, (uint32_t)q, o0, o1);
            s_kk[q][0] = o0; s_kk[q][1] = o1;
        }
        s_fgasc[0] = 0; s_hdasc[0] = 0; s_ezasc[0] = 0;
    }
    __syncthreads();

    for (int i = t; i < Mn; i += 256)
        s_u1[i] = u01(tf_bits32(s_kk[0][0], s_kk[0][1], (uint32_t)i));
    if (t < ROI) {
        s_u2[t] = u01(tf_bits32(s_kk[1][0], s_kk[1][1], (uint32_t)t));
        s_u3[t] = u01(tf_bits32(s_kk[2][0], s_kk[2][1], (uint32_t)t));
        s_u4[t] = u01(tf_bits32(s_kk[3][0], s_kk[3][1], (uint32_t)t));
    }

    for (int i = t; i < Mn; i += 256) {
        float mo = g_mo[b * Mn + i];
        s_mo[i] = mo;
        s_cat[i] = (mo >= 0.55f) ? 0 : ((mo < 0.1f) ? 2 : 1);
    }
    __syncthreads();

    // ballot-based ascending index lists per category
    for (int c = 0; c < 3; c++) {
        int* asc = (c == 0) ? s_fgasc : ((c == 1) ? s_hdasc : s_ezasc);
        for (int seg = 0; seg < 4; seg++) {
            int e = seg * 256 + t;
            bool mf = (s_cat[e] == c);
            unsigned bal = __ballot_sync(0xffffffffu, mf);
            if (lane == 0) s_ccnt[seg * 8 + warp] = __popc(bal);
        }
        __syncthreads();
        if (t == 0) {
            int acc = 0;
            for (int k = 0; k < 32; k++) { s_coff[k] = acc; acc += s_ccnt[k]; }
            s_coff[32] = acc;
            s_n[c] = acc;
        }
        __syncthreads();
        for (int seg = 0; seg < 4; seg++) {
            int e = seg * 256 + t;
            bool mf = (s_cat[e] == c);
            unsigned bal = __ballot_sync(0xffffffffu, mf);
            int rank = __popc(bal & ((1u << lane) - 1u));
            if (mf) asc[s_coff[seg * 8 + warp] + rank] = e;
        }
        __syncthreads();
    }

    // bitonic sort of (key, idx): key = fg ? u1 : 2.0, stable via idx tie-break
    for (int i = t; i < Mn; i += 256) {
        s_key[i] = (s_cat[i] == 0) ? s_u1[i] : 2.0f;
        s_sidx[i] = i;
    }
    __syncthreads();
    for (int k = 2; k <= Mn; k <<= 1) {
        for (int j2 = k >> 1; j2 > 0; j2 >>= 1) {
            for (int i = t; i < Mn; i += 256) {
                int ix = i ^ j2;
                if (ix > i) {
                    bool up = ((i & k) == 0);
                    float v1 = s_key[i], v2 = s_key[ix];
                    int i1 = s_sidx[i], i2 = s_sidx[ix];
                    bool gtr = (v1 > v2) || (v1 == v2 && i1 > i2);
                    if (gtr == up) {
                        s_key[i] = v2; s_key[ix] = v1;
                        s_sidx[i] = i2; s_sidx[ix] = i1;
                    }
                }
            }
            __syncthreads();
        }
    }

    int n_fg = s_n[0], n_hard = s_n[1], n_easy = s_n[2];
    int n_bg = n_hard + n_easy;
    int fg_this = (n_fg > 0) ? ((n_bg > 0) ? ((FGP < n_fg) ? FGP : n_fg) : ROI) : 0;
    int bg_this = ROI - fg_this;
    int hard_num = (n_hard > 0 && n_easy > 0) ? (int)((float)bg_this * 0.8f)
                 : ((n_hard > 0) ? bg_this : 0);

    if (t < ROI) {
        int j = t;
        int rand_fg = rpick(s_u2[j], s_fgasc, n_fg);
        int hp      = rpick(s_u3[j], s_hdasc, n_hard);
        int ep      = rpick(s_u4[j], s_ezasc, n_easy);
        int fg_idx = (n_bg > 0) ? s_sidx[j] : rand_fg;
        int bg_idx = ((j - fg_this) < hard_num) ? hp : ep;
        int idx = (j < fg_this) ? fg_idx : bg_idx;

        int gidx = b * Mn + idx;
        int base = b * ROI + j;
        float iou = s_mo[idx];

        const float* r = rois + (size_t)gidx * 7;
        float* o_r = out + (size_t)base * 7;
#pragma unroll
        for (int k = 0; k < 7; k++) o_r[k] = r[k];

        int asg = g_asgn[gidx];
        const float* g = gts + ((size_t)(b * Nn + asg)) * 8;
        float* o_g = out + 7168 + (size_t)base * 8;
#pragma unroll
        for (int k = 0; k < 8; k++) o_g[k] = g[k];

        out[15360 + base] = iou;
        out[16384 + base] = scores[gidx];
        out[17408 + base] = (float)labels[gidx];
        bool fgc = iou > 0.75f;
        bool bgc = iou < 0.25f;
        out[18432 + base] = (!fgc && !bgc) ? (iou * 2.0f - 0.5f) : (fgc ? 1.0f : 0.0f);
        out[19456 + base] = (iou > 0.55f) ? 1.0f : 0.0f;
    }
}

// ---------------------------------------------------------------------------
extern "C" void kernel_launch(void* const* d_in, const int* in_sizes, int n_in,
                              void* d_out, int out_size) {
    const float* rois   = (const float*)d_in[0];
    const float* gts    = (const float*)d_in[1];
    const float* scores = (const float*)d_in[2];
    const int*   labels = (const int*)d_in[3];
    float* out = (float*)d_out;

    iou_kernel<<<Bn * Mn, 128>>>(rois, gts);
    sample_kernel<<<Bn, 256>>>(rois, gts, scores, labels, out);
}